// round 5
// baseline (speedup 1.0000x reference)
#include <cuda_runtime.h>
#include <math.h>

// Problem constants
#define B_   4
#define L_   2048
#define D_   1024
#define H_   16
#define HD_  64
#define BH_  (B_*H_)
#define BL_  (B_*L_)
#define SCALE_ 0.125f   // 1/sqrt(64)

// ---------------- scratch (device globals; no allocation allowed) ----------
__device__ float g_qp [BL_ * D_];          // q projection  [b*l][1024]
__device__ float g_kvp[BL_ * 2 * D_];      // kv projection [b*l][2048]
__device__ float g_q  [BH_ * L_ * HD_];    // [b,h,l,hd] after rope
__device__ float g_k  [BH_ * L_ * HD_];
__device__ float g_v  [BH_ * L_ * HD_];
__device__ float g_attn[BL_ * D_];         // [b,l,h*hd]

// ---------------- fp32 SGEMM: C[M,N] = A[M,K] @ W[K,N] + bias --------------
// 128x128 tile, BK=8, 256 threads, 8x8 per thread.
__global__ void __launch_bounds__(256) sgemm_bias_kernel(
    const float* __restrict__ A, const float* __restrict__ W,
    const float* __restrict__ bias, float* __restrict__ C,
    int M, int N, int K)
{
    __shared__ float As[8][128];
    __shared__ float Bs[8][128];
    const int tid = threadIdx.x;
    const int tx = tid & 15, ty = tid >> 4;
    const int m0 = blockIdx.y << 7, n0 = blockIdx.x << 7;

    const int arow = tid >> 1;          // 0..127
    const int acol = (tid & 1) << 2;    // 0 or 4
    const int brow = tid >> 5;          // 0..7
    const int bcol = (tid & 31) << 2;   // 0..124

    const float* Ap = A + (size_t)(m0 + arow) * K + acol;
    const float* Wp = W + (size_t)brow * N + n0 + bcol;

    float acc[8][8];
#pragma unroll
    for (int i = 0; i < 8; i++)
#pragma unroll
        for (int j = 0; j < 8; j++) acc[i][j] = 0.f;

    for (int kt = 0; kt < K; kt += 8) {
        float4 av = *(const float4*)(Ap + kt);
        float4 bv = *(const float4*)(Wp + (size_t)kt * N);
        As[acol + 0][arow] = av.x;
        As[acol + 1][arow] = av.y;
        As[acol + 2][arow] = av.z;
        As[acol + 3][arow] = av.w;
        *(float4*)&Bs[brow][bcol] = bv;
        __syncthreads();
#pragma unroll
        for (int k = 0; k < 8; k++) {
            float4 a0 = *(const float4*)&As[k][ty << 3];
            float4 a1 = *(const float4*)&As[k][(ty << 3) + 4];
            float4 b0 = *(const float4*)&Bs[k][tx << 3];
            float4 b1 = *(const float4*)&Bs[k][(tx << 3) + 4];
            float a[8]  = {a0.x, a0.y, a0.z, a0.w, a1.x, a1.y, a1.z, a1.w};
            float bb[8] = {b0.x, b0.y, b0.z, b0.w, b1.x, b1.y, b1.z, b1.w};
#pragma unroll
            for (int i = 0; i < 8; i++)
#pragma unroll
                for (int j = 0; j < 8; j++)
                    acc[i][j] = fmaf(a[i], bb[j], acc[i][j]);
        }
        __syncthreads();
    }

    float bj[8];
#pragma unroll
    for (int j = 0; j < 8; j++) bj[j] = bias[n0 + (tx << 3) + j];
#pragma unroll
    for (int i = 0; i < 8; i++) {
        size_t row = (size_t)(m0 + (ty << 3) + i);
        float* Cp = C + row * N + n0 + (tx << 3);
        float4 o0 = make_float4(acc[i][0] + bj[0], acc[i][1] + bj[1],
                                acc[i][2] + bj[2], acc[i][3] + bj[3]);
        float4 o1 = make_float4(acc[i][4] + bj[4], acc[i][5] + bj[5],
                                acc[i][6] + bj[6], acc[i][7] + bj[7]);
        *(float4*)(Cp)     = o0;
        *(float4*)(Cp + 4) = o1;
    }
}

// ---------------- RoPE + head split/transpose ------------------------------
// One thread per (b,h,l,pair). rope[l, 2i] = sin, rope[l, 2i+1] = cos.
// Writes g_q/g_k/g_v in [b,h,l,hd] layout.
__global__ void __launch_bounds__(256) rope_split_kernel(const float* __restrict__ rope)
{
    int t = blockIdx.x * 256 + threadIdx.x;   // 0 .. B*H*L*32-1
    int i = t & 31;
    int l = (t >> 5) & (L_ - 1);
    int h = (t >> 16) & (H_ - 1);
    int b = t >> 20;

    float2 rp = ((const float2*)rope)[l * 32 + i];
    float sn = rp.x, cs = rp.y;

    const float2* qp2 = (const float2*)g_qp;
    const float2* kv2 = (const float2*)g_kvp;
    float2 q = qp2[(size_t)(b * L_ + l) * 512 + h * 32 + i];
    size_t kvbase = (size_t)(b * L_ + l) * 1024;
    float2 k = kv2[kvbase + h * 32 + i];
    float2 v = kv2[kvbase + 512 + h * 32 + i];

    float2 qo, ko;
    qo.x = q.x * cs - q.y * sn;  qo.y = q.x * sn + q.y * cs;
    ko.x = k.x * cs - k.y * sn;  ko.y = k.x * sn + k.y * cs;

    size_t o = (size_t)((b * H_ + h) * L_ + l) * 32 + i;
    ((float2*)g_q)[o] = qo;
    ((float2*)g_k)[o] = ko;
    ((float2*)g_v)[o] = v;
}

// ---------------- causal flash attention (fp32 SIMT) -----------------------
// BM=BN=64, HD=64. 256 threads = 16x16, 4x4 outputs/thread.
#define FBM 64
#define FBN 64
#define FPAD 68
#define FLASH_SMEM ((64*FPAD /*Qt*/ + 64*FPAD /*Kt*/ + FBN*64 /*V*/ + FBM*FPAD /*P*/) * 4)

__global__ void __launch_bounds__(256) flash_kernel()
{
    extern __shared__ float sm[];
    float (*sQt)[FPAD] = (float(*)[FPAD])sm;                       // [hd][row]
    float (*sKt)[FPAD] = (float(*)[FPAD])(sm + 64 * FPAD);         // [hd][col]
    float (*sV)[64]    = (float(*)[64])  (sm + 2 * 64 * FPAD);     // [n][hd]
    float (*sP)[FPAD]  = (float(*)[FPAD])(sm + 2 * 64 * FPAD + FBN * 64);

    const int tid = threadIdx.x;
    const int tx = tid & 15, ty = tid >> 4;
    const int qb = blockIdx.x;            // query block (32)
    const int bh = blockIdx.y;            // 0..63
    const int q0 = qb * FBM;
    const int b = bh >> 4, h = bh & 15;

    const float* Qb = g_q + ((size_t)bh * L_ + q0) * HD_;
    const float* Kb = g_k + (size_t)bh * L_ * HD_;
    const float* Vb = g_v + (size_t)bh * L_ * HD_;

    // Q tile -> transposed smem (once per block)
#pragma unroll
    for (int u = 0; u < 4; u++) {
        int idx = tid + 256 * u;
        int r = idx >> 4;
        int c = (idx & 15) << 2;
        float4 qv = *(const float4*)(Qb + (size_t)r * HD_ + c);
        sQt[c + 0][r] = qv.x; sQt[c + 1][r] = qv.y;
        sQt[c + 2][r] = qv.z; sQt[c + 3][r] = qv.w;
    }

    float m_i[4], l_i[4], Oa[4][4];
#pragma unroll
    for (int i = 0; i < 4; i++) {
        m_i[i] = -INFINITY; l_i[i] = 0.f;
#pragma unroll
        for (int j = 0; j < 4; j++) Oa[i][j] = 0.f;
    }

    for (int kb = 0; kb <= qb; kb++) {
        const int n0 = kb * FBN;
        // K tile transposed + V tile natural
#pragma unroll
        for (int u = 0; u < 4; u++) {
            int idx = tid + 256 * u;
            int r = idx >> 4;
            int c = (idx & 15) << 2;
            float4 kv = *(const float4*)(Kb + (size_t)(n0 + r) * HD_ + c);
            sKt[c + 0][r] = kv.x; sKt[c + 1][r] = kv.y;
            sKt[c + 2][r] = kv.z; sKt[c + 3][r] = kv.w;
            float4 vv = *(const float4*)(Vb + (size_t)(n0 + r) * HD_ + c);
            *(float4*)&sV[r][c] = vv;
        }
        __syncthreads();

        // S = Q K^T (4x4 per thread)
        float S[4][4];
#pragma unroll
        for (int i = 0; i < 4; i++)
#pragma unroll
            for (int j = 0; j < 4; j++) S[i][j] = 0.f;

#pragma unroll 8
        for (int kk = 0; kk < HD_; kk++) {
            float4 a  = *(const float4*)&sQt[kk][ty << 2];
            float4 bb = *(const float4*)&sKt[kk][tx << 2];
            float av[4] = {a.x, a.y, a.z, a.w};
            float bv[4] = {bb.x, bb.y, bb.z, bb.w};
#pragma unroll
            for (int i = 0; i < 4; i++)
#pragma unroll
                for (int j = 0; j < 4; j++)
                    S[i][j] = fmaf(av[i], bv[j], S[i][j]);
        }

        const bool diag = (kb == qb);
#pragma unroll
        for (int i = 0; i < 4; i++) {
            int row = q0 + (ty << 2) + i;
#pragma unroll
            for (int j = 0; j < 4; j++) {
                float s = S[i][j] * SCALE_;
                if (diag && (n0 + (tx << 2) + j > row)) s = -1e9f;
                S[i][j] = s;
            }
        }

        // online softmax; rows are shared by the 16 tx-lanes (shuffle width 16)
#pragma unroll
        for (int i = 0; i < 4; i++) {
            float rm = fmaxf(fmaxf(S[i][0], S[i][1]), fmaxf(S[i][2], S[i][3]));
#pragma unroll
            for (int off = 8; off >= 1; off >>= 1)
                rm = fmaxf(rm, __shfl_xor_sync(0xffffffffu, rm, off, 16));
            float mn = fmaxf(m_i[i], rm);
            float corr = __expf(m_i[i] - mn);
            float ps = 0.f;
#pragma unroll
            for (int j = 0; j < 4; j++) {
                float p = __expf(S[i][j] - mn);
                S[i][j] = p;
                ps += p;
            }
#pragma unroll
            for (int off = 8; off >= 1; off >>= 1)
                ps += __shfl_xor_sync(0xffffffffu, ps, off, 16);
            l_i[i] = l_i[i] * corr + ps;
            m_i[i] = mn;
#pragma unroll
            for (int j = 0; j < 4; j++) Oa[i][j] *= corr;
            *(float4*)&sP[(ty << 2) + i][tx << 2] =
                make_float4(S[i][0], S[i][1], S[i][2], S[i][3]);
        }
        __syncthreads();

        // O += P @ V
#pragma unroll 4
        for (int n4 = 0; n4 < FBN; n4 += 4) {
            float4 p0 = *(const float4*)&sP[(ty << 2) + 0][n4];
            float4 p1 = *(const float4*)&sP[(ty << 2) + 1][n4];
            float4 p2 = *(const float4*)&sP[(ty << 2) + 2][n4];
            float4 p3 = *(const float4*)&sP[(ty << 2) + 3][n4];
            float4 v0 = *(const float4*)&sV[n4 + 0][tx << 2];
            float4 v1 = *(const float4*)&sV[n4 + 1][tx << 2];
            float4 v2 = *(const float4*)&sV[n4 + 2][tx << 2];
            float4 v3 = *(const float4*)&sV[n4 + 3][tx << 2];
            float pr[4][4] = {{p0.x,p0.y,p0.z,p0.w},{p1.x,p1.y,p1.z,p1.w},
                              {p2.x,p2.y,p2.z,p2.w},{p3.x,p3.y,p3.z,p3.w}};
            float vr[4][4] = {{v0.x,v0.y,v0.z,v0.w},{v1.x,v1.y,v1.z,v1.w},
                              {v2.x,v2.y,v2.z,v2.w},{v3.x,v3.y,v3.z,v3.w}};
#pragma unroll
            for (int i = 0; i < 4; i++)
#pragma unroll
                for (int j = 0; j < 4; j++) {
                    float acc = Oa[i][j];
#pragma unroll
                    for (int n = 0; n < 4; n++)
                        acc = fmaf(pr[i][n], vr[n][j], acc);
                    Oa[i][j] = acc;
                }
        }
        __syncthreads();
    }

    // normalize + write [b,l,h*hd]
#pragma unroll
    for (int i = 0; i < 4; i++) {
        int row = q0 + (ty << 2) + i;
        float inv = 1.f / l_i[i];
        float4 o = make_float4(Oa[i][0] * inv, Oa[i][1] * inv,
                               Oa[i][2] * inv, Oa[i][3] * inv);
        *(float4*)&g_attn[(size_t)(b * L_ + row) * D_ + h * HD_ + (tx << 2)] = o;
    }
}

// ---------------- launch ----------------------------------------------------
extern "C" void kernel_launch(void* const* d_in, const int* in_sizes, int n_in,
                              void* d_out, int out_size)
{
    const float* q_in = (const float*)d_in[0];
    const float* k_in = (const float*)d_in[1];
    // d_in[2] = v_in (unused by reference), d_in[3] = mask (tril, hardcoded causal)
    const float* rope = (const float*)d_in[4];
    const float* Wq   = (const float*)d_in[5];
    const float* bq   = (const float*)d_in[6];
    const float* Wkv  = (const float*)d_in[7];
    const float* bkv  = (const float*)d_in[8];
    const float* Wp   = (const float*)d_in[9];
    const float* bp   = (const float*)d_in[10];
    float* out = (float*)d_out;

    float *qp, *kvp, *attn;
    cudaGetSymbolAddress((void**)&qp,   g_qp);
    cudaGetSymbolAddress((void**)&kvp,  g_kvp);
    cudaGetSymbolAddress((void**)&attn, g_attn);

    // 1) Q projection: [8192,1024] = q_in @ Wq + bq
    sgemm_bias_kernel<<<dim3(D_ / 128, BL_ / 128), 256>>>(q_in, Wq, bq, qp, BL_, D_, D_);
    // 2) KV projection: [8192,2048] = k_in @ Wkv + bkv
    sgemm_bias_kernel<<<dim3(2 * D_ / 128, BL_ / 128), 256>>>(k_in, Wkv, bkv, kvp, BL_, 2 * D_, D_);
    // 3) RoPE + split + transpose to [b,h,l,hd]
    rope_split_kernel<<<(B_ * H_ * L_ * 32) / 256, 256>>>(rope);
    // 4) causal flash attention
    cudaFuncSetAttribute(flash_kernel, cudaFuncAttributeMaxDynamicSharedMemorySize, FLASH_SMEM);
    flash_kernel<<<dim3(L_ / FBM, BH_), 256, FLASH_SMEM>>>();
    // 5) output projection: out = attn @ Wp + bp
    sgemm_bias_kernel<<<dim3(D_ / 128, BL_ / 128), 256>>>(attn, Wp, bp, out, BL_, D_, D_);
}

// round 6
// speedup vs baseline: 1.0029x; 1.0029x over previous
#include <cuda_runtime.h>
#include <math.h>

// Problem constants
#define B_   4
#define L_   2048
#define D_   1024
#define H_   16
#define HD_  64
#define BH_  (B_*H_)
#define BL_  (B_*L_)
#define SCALE_ 0.125f   // 1/sqrt(64)

// ---------------- scratch (device globals; no allocation allowed) ----------
__device__ float g_qp [BL_ * D_];          // q projection  [b*l][1024]
__device__ float g_kvp[BL_ * 2 * D_];      // kv projection [b*l][2048]
__device__ float g_q  [BH_ * L_ * HD_];    // [b,h,l,hd] after rope
__device__ float g_k  [BH_ * L_ * HD_];
__device__ float g_v  [BH_ * L_ * HD_];
__device__ float g_attn[BL_ * D_];         // [b,l,h*hd]

// ---------------- fp32 SGEMM: C[M,N] = A[M,K] @ W[K,N] + bias --------------
// 128x128 tile, BK=8, 256 threads, 8x8 per thread.
__global__ void __launch_bounds__(256) sgemm_bias_kernel(
    const float* __restrict__ A, const float* __restrict__ W,
    const float* __restrict__ bias, float* __restrict__ C,
    int M, int N, int K)
{
    __shared__ float As[8][128];
    __shared__ float Bs[8][128];
    const int tid = threadIdx.x;
    const int tx = tid & 15, ty = tid >> 4;
    const int m0 = blockIdx.y << 7, n0 = blockIdx.x << 7;

    const int arow = tid >> 1;          // 0..127
    const int acol = (tid & 1) << 2;    // 0 or 4
    const int brow = tid >> 5;          // 0..7
    const int bcol = (tid & 31) << 2;   // 0..124

    const float* Ap = A + (size_t)(m0 + arow) * K + acol;
    const float* Wp = W + (size_t)brow * N + n0 + bcol;

    float acc[8][8];
#pragma unroll
    for (int i = 0; i < 8; i++)
#pragma unroll
        for (int j = 0; j < 8; j++) acc[i][j] = 0.f;

    for (int kt = 0; kt < K; kt += 8) {
        float4 av = *(const float4*)(Ap + kt);
        float4 bv = *(const float4*)(Wp + (size_t)kt * N);
        As[acol + 0][arow] = av.x;
        As[acol + 1][arow] = av.y;
        As[acol + 2][arow] = av.z;
        As[acol + 3][arow] = av.w;
        *(float4*)&Bs[brow][bcol] = bv;
        __syncthreads();
#pragma unroll
        for (int k = 0; k < 8; k++) {
            float4 a0 = *(const float4*)&As[k][ty << 3];
            float4 a1 = *(const float4*)&As[k][(ty << 3) + 4];
            float4 b0 = *(const float4*)&Bs[k][tx << 3];
            float4 b1 = *(const float4*)&Bs[k][(tx << 3) + 4];
            float a[8]  = {a0.x, a0.y, a0.z, a0.w, a1.x, a1.y, a1.z, a1.w};
            float bb[8] = {b0.x, b0.y, b0.z, b0.w, b1.x, b1.y, b1.z, b1.w};
#pragma unroll
            for (int i = 0; i < 8; i++)
#pragma unroll
                for (int j = 0; j < 8; j++)
                    acc[i][j] = fmaf(a[i], bb[j], acc[i][j]);
        }
        __syncthreads();
    }

    float bj[8];
#pragma unroll
    for (int j = 0; j < 8; j++) bj[j] = bias[n0 + (tx << 3) + j];
#pragma unroll
    for (int i = 0; i < 8; i++) {
        size_t row = (size_t)(m0 + (ty << 3) + i);
        float* Cp = C + row * N + n0 + (tx << 3);
        float4 o0 = make_float4(acc[i][0] + bj[0], acc[i][1] + bj[1],
                                acc[i][2] + bj[2], acc[i][3] + bj[3]);
        float4 o1 = make_float4(acc[i][4] + bj[4], acc[i][5] + bj[5],
                                acc[i][6] + bj[6], acc[i][7] + bj[7]);
        *(float4*)(Cp)     = o0;
        *(float4*)(Cp + 4) = o1;
    }
}

// ---------------- RoPE + head split/transpose ------------------------------
// One thread per (b,h,l,pair). rope[l, 2i] = sin, rope[l, 2i+1] = cos.
// Writes g_q/g_k/g_v in [b,h,l,hd] layout.
__global__ void __launch_bounds__(256) rope_split_kernel(const float* __restrict__ rope)
{
    int t = blockIdx.x * 256 + threadIdx.x;   // 0 .. B*H*L*32-1
    int i = t & 31;
    int l = (t >> 5) & (L_ - 1);
    int h = (t >> 16) & (H_ - 1);
    int b = t >> 20;

    float2 rp = ((const float2*)rope)[l * 32 + i];
    float sn = rp.x, cs = rp.y;

    const float2* qp2 = (const float2*)g_qp;
    const float2* kv2 = (const float2*)g_kvp;
    float2 q = qp2[(size_t)(b * L_ + l) * 512 + h * 32 + i];
    size_t kvbase = (size_t)(b * L_ + l) * 1024;
    float2 k = kv2[kvbase + h * 32 + i];
    float2 v = kv2[kvbase + 512 + h * 32 + i];

    float2 qo, ko;
    qo.x = q.x * cs - q.y * sn;  qo.y = q.x * sn + q.y * cs;
    ko.x = k.x * cs - k.y * sn;  ko.y = k.x * sn + k.y * cs;

    size_t o = (size_t)((b * H_ + h) * L_ + l) * 32 + i;
    ((float2*)g_q)[o] = qo;
    ((float2*)g_k)[o] = ko;
    ((float2*)g_v)[o] = v;
}

// ---------------- causal flash attention (fp32 SIMT) -----------------------
// BM=BN=64, HD=64. 256 threads = 16x16, 4x4 outputs/thread.
#define FBM 64
#define FBN 64
#define FPAD 68
#define FLASH_SMEM ((64*FPAD /*Qt*/ + 64*FPAD /*Kt*/ + FBN*64 /*V*/ + FBM*FPAD /*P*/) * 4)

__global__ void __launch_bounds__(256) flash_kernel()
{
    extern __shared__ float sm[];
    float (*sQt)[FPAD] = (float(*)[FPAD])sm;                       // [hd][row]
    float (*sKt)[FPAD] = (float(*)[FPAD])(sm + 64 * FPAD);         // [hd][col]
    float (*sV)[64]    = (float(*)[64])  (sm + 2 * 64 * FPAD);     // [n][hd]
    float (*sP)[FPAD]  = (float(*)[FPAD])(sm + 2 * 64 * FPAD + FBN * 64);

    const int tid = threadIdx.x;
    const int tx = tid & 15, ty = tid >> 4;
    const int qb = blockIdx.x;            // query block (32)
    const int bh = blockIdx.y;            // 0..63
    const int q0 = qb * FBM;
    const int b = bh >> 4, h = bh & 15;

    const float* Qb = g_q + ((size_t)bh * L_ + q0) * HD_;
    const float* Kb = g_k + (size_t)bh * L_ * HD_;
    const float* Vb = g_v + (size_t)bh * L_ * HD_;

    // Q tile -> transposed smem (once per block)
#pragma unroll
    for (int u = 0; u < 4; u++) {
        int idx = tid + 256 * u;
        int r = idx >> 4;
        int c = (idx & 15) << 2;
        float4 qv = *(const float4*)(Qb + (size_t)r * HD_ + c);
        sQt[c + 0][r] = qv.x; sQt[c + 1][r] = qv.y;
        sQt[c + 2][r] = qv.z; sQt[c + 3][r] = qv.w;
    }

    float m_i[4], l_i[4], Oa[4][4];
#pragma unroll
    for (int i = 0; i < 4; i++) {
        m_i[i] = -INFINITY; l_i[i] = 0.f;
#pragma unroll
        for (int j = 0; j < 4; j++) Oa[i][j] = 0.f;
    }

    for (int kb = 0; kb <= qb; kb++) {
        const int n0 = kb * FBN;
        // K tile transposed + V tile natural
#pragma unroll
        for (int u = 0; u < 4; u++) {
            int idx = tid + 256 * u;
            int r = idx >> 4;
            int c = (idx & 15) << 2;
            float4 kv = *(const float4*)(Kb + (size_t)(n0 + r) * HD_ + c);
            sKt[c + 0][r] = kv.x; sKt[c + 1][r] = kv.y;
            sKt[c + 2][r] = kv.z; sKt[c + 3][r] = kv.w;
            float4 vv = *(const float4*)(Vb + (size_t)(n0 + r) * HD_ + c);
            *(float4*)&sV[r][c] = vv;
        }
        __syncthreads();

        // S = Q K^T (4x4 per thread)
        float S[4][4];
#pragma unroll
        for (int i = 0; i < 4; i++)
#pragma unroll
            for (int j = 0; j < 4; j++) S[i][j] = 0.f;

#pragma unroll 8
        for (int kk = 0; kk < HD_; kk++) {
            float4 a  = *(const float4*)&sQt[kk][ty << 2];
            float4 bb = *(const float4*)&sKt[kk][tx << 2];
            float av[4] = {a.x, a.y, a.z, a.w};
            float bv[4] = {bb.x, bb.y, bb.z, bb.w};
#pragma unroll
            for (int i = 0; i < 4; i++)
#pragma unroll
                for (int j = 0; j < 4; j++)
                    S[i][j] = fmaf(av[i], bv[j], S[i][j]);
        }

        const bool diag = (kb == qb);
#pragma unroll
        for (int i = 0; i < 4; i++) {
            int row = q0 + (ty << 2) + i;
#pragma unroll
            for (int j = 0; j < 4; j++) {
                float s = S[i][j] * SCALE_;
                if (diag && (n0 + (tx << 2) + j > row)) s = -1e9f;
                S[i][j] = s;
            }
        }

        // online softmax; rows are shared by the 16 tx-lanes (shuffle width 16)
#pragma unroll
        for (int i = 0; i < 4; i++) {
            float rm = fmaxf(fmaxf(S[i][0], S[i][1]), fmaxf(S[i][2], S[i][3]));
#pragma unroll
            for (int off = 8; off >= 1; off >>= 1)
                rm = fmaxf(rm, __shfl_xor_sync(0xffffffffu, rm, off, 16));
            float mn = fmaxf(m_i[i], rm);
            float corr = __expf(m_i[i] - mn);
            float ps = 0.f;
#pragma unroll
            for (int j = 0; j < 4; j++) {
                float p = __expf(S[i][j] - mn);
                S[i][j] = p;
                ps += p;
            }
#pragma unroll
            for (int off = 8; off >= 1; off >>= 1)
                ps += __shfl_xor_sync(0xffffffffu, ps, off, 16);
            l_i[i] = l_i[i] * corr + ps;
            m_i[i] = mn;
#pragma unroll
            for (int j = 0; j < 4; j++) Oa[i][j] *= corr;
            *(float4*)&sP[(ty << 2) + i][tx << 2] =
                make_float4(S[i][0], S[i][1], S[i][2], S[i][3]);
        }
        __syncthreads();

        // O += P @ V
#pragma unroll 4
        for (int n4 = 0; n4 < FBN; n4 += 4) {
            float4 p0 = *(const float4*)&sP[(ty << 2) + 0][n4];
            float4 p1 = *(const float4*)&sP[(ty << 2) + 1][n4];
            float4 p2 = *(const float4*)&sP[(ty << 2) + 2][n4];
            float4 p3 = *(const float4*)&sP[(ty << 2) + 3][n4];
            float4 v0 = *(const float4*)&sV[n4 + 0][tx << 2];
            float4 v1 = *(const float4*)&sV[n4 + 1][tx << 2];
            float4 v2 = *(const float4*)&sV[n4 + 2][tx << 2];
            float4 v3 = *(const float4*)&sV[n4 + 3][tx << 2];
            float pr[4][4] = {{p0.x,p0.y,p0.z,p0.w},{p1.x,p1.y,p1.z,p1.w},
                              {p2.x,p2.y,p2.z,p2.w},{p3.x,p3.y,p3.z,p3.w}};
            float vr[4][4] = {{v0.x,v0.y,v0.z,v0.w},{v1.x,v1.y,v1.z,v1.w},
                              {v2.x,v2.y,v2.z,v2.w},{v3.x,v3.y,v3.z,v3.w}};
#pragma unroll
            for (int i = 0; i < 4; i++)
#pragma unroll
                for (int j = 0; j < 4; j++) {
                    float acc = Oa[i][j];
#pragma unroll
                    for (int n = 0; n < 4; n++)
                        acc = fmaf(pr[i][n], vr[n][j], acc);
                    Oa[i][j] = acc;
                }
        }
        __syncthreads();
    }

    // normalize + write [b,l,h*hd]
#pragma unroll
    for (int i = 0; i < 4; i++) {
        int row = q0 + (ty << 2) + i;
        float inv = 1.f / l_i[i];
        float4 o = make_float4(Oa[i][0] * inv, Oa[i][1] * inv,
                               Oa[i][2] * inv, Oa[i][3] * inv);
        *(float4*)&g_attn[(size_t)(b * L_ + row) * D_ + h * HD_ + (tx << 2)] = o;
    }
}

// ---------------- launch ----------------------------------------------------
extern "C" void kernel_launch(void* const* d_in, const int* in_sizes, int n_in,
                              void* d_out, int out_size)
{
    const float* q_in = (const float*)d_in[0];
    const float* k_in = (const float*)d_in[1];
    // d_in[2] = v_in (unused by reference), d_in[3] = mask (tril, hardcoded causal)
    const float* rope = (const float*)d_in[4];
    const float* Wq   = (const float*)d_in[5];
    const float* bq   = (const float*)d_in[6];
    const float* Wkv  = (const float*)d_in[7];
    const float* bkv  = (const float*)d_in[8];
    const float* Wp   = (const float*)d_in[9];
    const float* bp   = (const float*)d_in[10];
    float* out = (float*)d_out;

    float *qp, *kvp, *attn;
    cudaGetSymbolAddress((void**)&qp,   g_qp);
    cudaGetSymbolAddress((void**)&kvp,  g_kvp);
    cudaGetSymbolAddress((void**)&attn, g_attn);

    // 1) Q projection: [8192,1024] = q_in @ Wq + bq
    sgemm_bias_kernel<<<dim3(D_ / 128, BL_ / 128), 256>>>(q_in, Wq, bq, qp, BL_, D_, D_);
    // 2) KV projection: [8192,2048] = k_in @ Wkv + bkv
    sgemm_bias_kernel<<<dim3(2 * D_ / 128, BL_ / 128), 256>>>(k_in, Wkv, bkv, kvp, BL_, 2 * D_, D_);
    // 3) RoPE + split + transpose to [b,h,l,hd]
    rope_split_kernel<<<(B_ * H_ * L_ * 32) / 256, 256>>>(rope);
    // 4) causal flash attention
    cudaFuncSetAttribute(flash_kernel, cudaFuncAttributeMaxDynamicSharedMemorySize, FLASH_SMEM);
    flash_kernel<<<dim3(L_ / FBM, BH_), 256, FLASH_SMEM>>>();
    // 5) output projection: out = attn @ Wp + bp
    sgemm_bias_kernel<<<dim3(D_ / 128, BL_ / 128), 256>>>(attn, Wp, bp, out, BL_, D_, D_);
}

// round 7
// speedup vs baseline: 1.0088x; 1.0059x over previous
#include <cuda_runtime.h>
#include <math.h>

// Problem constants
#define B_   4
#define L_   2048
#define D_   1024
#define H_   16
#define HD_  64
#define BH_  (B_*H_)
#define BL_  (B_*L_)
#define SCALE_ 0.125f   // 1/sqrt(64)

// ---------------- scratch (device globals; no allocation allowed) ----------
__device__ float g_qp [BL_ * D_];          // q projection  [b*l][1024]
__device__ float g_kvp[BL_ * 2 * D_];      // kv projection [b*l][2048]
__device__ float g_q  [BH_ * L_ * HD_];    // [b,h,l,hd] after rope
__device__ float g_k  [BH_ * L_ * HD_];
__device__ float g_v  [BH_ * L_ * HD_];
__device__ float g_attn[BL_ * D_];         // [b,l,h*hd]

// ---------------- fp32 SGEMM: C[M,N] = A[M,K] @ W[K,N] + bias --------------
// 128x128 tile, BK=8, 256 threads, 8x8 per thread.
__global__ void __launch_bounds__(256) sgemm_bias_kernel(
    const float* __restrict__ A, const float* __restrict__ W,
    const float* __restrict__ bias, float* __restrict__ C,
    int M, int N, int K)
{
    __shared__ float As[8][128];
    __shared__ float Bs[8][128];
    const int tid = threadIdx.x;
    const int tx = tid & 15, ty = tid >> 4;
    const int m0 = blockIdx.y << 7, n0 = blockIdx.x << 7;

    const int arow = tid >> 1;          // 0..127
    const int acol = (tid & 1) << 2;    // 0 or 4
    const int brow = tid >> 5;          // 0..7
    const int bcol = (tid & 31) << 2;   // 0..124

    const float* Ap = A + (size_t)(m0 + arow) * K + acol;
    const float* Wp = W + (size_t)brow * N + n0 + bcol;

    float acc[8][8];
#pragma unroll
    for (int i = 0; i < 8; i++)
#pragma unroll
        for (int j = 0; j < 8; j++) acc[i][j] = 0.f;

    for (int kt = 0; kt < K; kt += 8) {
        float4 av = *(const float4*)(Ap + kt);
        float4 bv = *(const float4*)(Wp + (size_t)kt * N);
        As[acol + 0][arow] = av.x;
        As[acol + 1][arow] = av.y;
        As[acol + 2][arow] = av.z;
        As[acol + 3][arow] = av.w;
        *(float4*)&Bs[brow][bcol] = bv;
        __syncthreads();
#pragma unroll
        for (int k = 0; k < 8; k++) {
            float4 a0 = *(const float4*)&As[k][ty << 3];
            float4 a1 = *(const float4*)&As[k][(ty << 3) + 4];
            float4 b0 = *(const float4*)&Bs[k][tx << 3];
            float4 b1 = *(const float4*)&Bs[k][(tx << 3) + 4];
            float a[8]  = {a0.x, a0.y, a0.z, a0.w, a1.x, a1.y, a1.z, a1.w};
            float bb[8] = {b0.x, b0.y, b0.z, b0.w, b1.x, b1.y, b1.z, b1.w};
#pragma unroll
            for (int i = 0; i < 8; i++)
#pragma unroll
                for (int j = 0; j < 8; j++)
                    acc[i][j] = fmaf(a[i], bb[j], acc[i][j]);
        }
        __syncthreads();
    }

    float bj[8];
#pragma unroll
    for (int j = 0; j < 8; j++) bj[j] = bias[n0 + (tx << 3) + j];
#pragma unroll
    for (int i = 0; i < 8; i++) {
        size_t row = (size_t)(m0 + (ty << 3) + i);
        float* Cp = C + row * N + n0 + (tx << 3);
        float4 o0 = make_float4(acc[i][0] + bj[0], acc[i][1] + bj[1],
                                acc[i][2] + bj[2], acc[i][3] + bj[3]);
        float4 o1 = make_float4(acc[i][4] + bj[4], acc[i][5] + bj[5],
                                acc[i][6] + bj[6], acc[i][7] + bj[7]);
        *(float4*)(Cp)     = o0;
        *(float4*)(Cp + 4) = o1;
    }
}

// ---------------- RoPE + head split/transpose ------------------------------
// One thread per (b,h,l,pair). rope[l, 2i] = sin, rope[l, 2i+1] = cos.
// Writes g_q/g_k/g_v in [b,h,l,hd] layout.
__global__ void __launch_bounds__(256) rope_split_kernel(const float* __restrict__ rope)
{
    int t = blockIdx.x * 256 + threadIdx.x;   // 0 .. B*H*L*32-1
    int i = t & 31;
    int l = (t >> 5) & (L_ - 1);
    int h = (t >> 16) & (H_ - 1);
    int b = t >> 20;

    float2 rp = ((const float2*)rope)[l * 32 + i];
    float sn = rp.x, cs = rp.y;

    const float2* qp2 = (const float2*)g_qp;
    const float2* kv2 = (const float2*)g_kvp;
    float2 q = qp2[(size_t)(b * L_ + l) * 512 + h * 32 + i];
    size_t kvbase = (size_t)(b * L_ + l) * 1024;
    float2 k = kv2[kvbase + h * 32 + i];
    float2 v = kv2[kvbase + 512 + h * 32 + i];

    float2 qo, ko;
    qo.x = q.x * cs - q.y * sn;  qo.y = q.x * sn + q.y * cs;
    ko.x = k.x * cs - k.y * sn;  ko.y = k.x * sn + k.y * cs;

    size_t o = (size_t)((b * H_ + h) * L_ + l) * 32 + i;
    ((float2*)g_q)[o] = qo;
    ((float2*)g_k)[o] = ko;
    ((float2*)g_v)[o] = v;
}

// ---------------- causal flash attention (fp32 SIMT) -----------------------
// BM=BN=64, HD=64. 256 threads = 16x16, 4x4 outputs/thread.
#define FBM 64
#define FBN 64
#define FPAD 68
#define FLASH_SMEM ((64*FPAD /*Qt*/ + 64*FPAD /*Kt*/ + FBN*64 /*V*/ + FBM*FPAD /*P*/) * 4)

__global__ void __launch_bounds__(256) flash_kernel()
{
    extern __shared__ float sm[];
    float (*sQt)[FPAD] = (float(*)[FPAD])sm;                       // [hd][row]
    float (*sKt)[FPAD] = (float(*)[FPAD])(sm + 64 * FPAD);         // [hd][col]
    float (*sV)[64]    = (float(*)[64])  (sm + 2 * 64 * FPAD);     // [n][hd]
    float (*sP)[FPAD]  = (float(*)[FPAD])(sm + 2 * 64 * FPAD + FBN * 64);

    const int tid = threadIdx.x;
    const int tx = tid & 15, ty = tid >> 4;
    const int qb = blockIdx.x;            // query block (32)
    const int bh = blockIdx.y;            // 0..63
    const int q0 = qb * FBM;
    const int b = bh >> 4, h = bh & 15;

    const float* Qb = g_q + ((size_t)bh * L_ + q0) * HD_;
    const float* Kb = g_k + (size_t)bh * L_ * HD_;
    const float* Vb = g_v + (size_t)bh * L_ * HD_;

    // Q tile -> transposed smem (once per block)
#pragma unroll
    for (int u = 0; u < 4; u++) {
        int idx = tid + 256 * u;
        int r = idx >> 4;
        int c = (idx & 15) << 2;
        float4 qv = *(const float4*)(Qb + (size_t)r * HD_ + c);
        sQt[c + 0][r] = qv.x; sQt[c + 1][r] = qv.y;
        sQt[c + 2][r] = qv.z; sQt[c + 3][r] = qv.w;
    }

    float m_i[4], l_i[4], Oa[4][4];
#pragma unroll
    for (int i = 0; i < 4; i++) {
        m_i[i] = -INFINITY; l_i[i] = 0.f;
#pragma unroll
        for (int j = 0; j < 4; j++) Oa[i][j] = 0.f;
    }

    for (int kb = 0; kb <= qb; kb++) {
        const int n0 = kb * FBN;
        // K tile transposed + V tile natural
#pragma unroll
        for (int u = 0; u < 4; u++) {
            int idx = tid + 256 * u;
            int r = idx >> 4;
            int c = (idx & 15) << 2;
            float4 kv = *(const float4*)(Kb + (size_t)(n0 + r) * HD_ + c);
            sKt[c + 0][r] = kv.x; sKt[c + 1][r] = kv.y;
            sKt[c + 2][r] = kv.z; sKt[c + 3][r] = kv.w;
            float4 vv = *(const float4*)(Vb + (size_t)(n0 + r) * HD_ + c);
            *(float4*)&sV[r][c] = vv;
        }
        __syncthreads();

        // S = Q K^T (4x4 per thread)
        float S[4][4];
#pragma unroll
        for (int i = 0; i < 4; i++)
#pragma unroll
            for (int j = 0; j < 4; j++) S[i][j] = 0.f;

#pragma unroll 8
        for (int kk = 0; kk < HD_; kk++) {
            float4 a  = *(const float4*)&sQt[kk][ty << 2];
            float4 bb = *(const float4*)&sKt[kk][tx << 2];
            float av[4] = {a.x, a.y, a.z, a.w};
            float bv[4] = {bb.x, bb.y, bb.z, bb.w};
#pragma unroll
            for (int i = 0; i < 4; i++)
#pragma unroll
                for (int j = 0; j < 4; j++)
                    S[i][j] = fmaf(av[i], bv[j], S[i][j]);
        }

        const bool diag = (kb == qb);
#pragma unroll
        for (int i = 0; i < 4; i++) {
            int row = q0 + (ty << 2) + i;
#pragma unroll
            for (int j = 0; j < 4; j++) {
                float s = S[i][j] * SCALE_;
                if (diag && (n0 + (tx << 2) + j > row)) s = -1e9f;
                S[i][j] = s;
            }
        }

        // online softmax; rows are shared by the 16 tx-lanes (shuffle width 16)
#pragma unroll
        for (int i = 0; i < 4; i++) {
            float rm = fmaxf(fmaxf(S[i][0], S[i][1]), fmaxf(S[i][2], S[i][3]));
#pragma unroll
            for (int off = 8; off >= 1; off >>= 1)
                rm = fmaxf(rm, __shfl_xor_sync(0xffffffffu, rm, off, 16));
            float mn = fmaxf(m_i[i], rm);
            float corr = __expf(m_i[i] - mn);
            float ps = 0.f;
#pragma unroll
            for (int j = 0; j < 4; j++) {
                float p = __expf(S[i][j] - mn);
                S[i][j] = p;
                ps += p;
            }
#pragma unroll
            for (int off = 8; off >= 1; off >>= 1)
                ps += __shfl_xor_sync(0xffffffffu, ps, off, 16);
            l_i[i] = l_i[i] * corr + ps;
            m_i[i] = mn;
#pragma unroll
            for (int j = 0; j < 4; j++) Oa[i][j] *= corr;
            *(float4*)&sP[(ty << 2) + i][tx << 2] =
                make_float4(S[i][0], S[i][1], S[i][2], S[i][3]);
        }
        __syncthreads();

        // O += P @ V
#pragma unroll 4
        for (int n4 = 0; n4 < FBN; n4 += 4) {
            float4 p0 = *(const float4*)&sP[(ty << 2) + 0][n4];
            float4 p1 = *(const float4*)&sP[(ty << 2) + 1][n4];
            float4 p2 = *(const float4*)&sP[(ty << 2) + 2][n4];
            float4 p3 = *(const float4*)&sP[(ty << 2) + 3][n4];
            float4 v0 = *(const float4*)&sV[n4 + 0][tx << 2];
            float4 v1 = *(const float4*)&sV[n4 + 1][tx << 2];
            float4 v2 = *(const float4*)&sV[n4 + 2][tx << 2];
            float4 v3 = *(const float4*)&sV[n4 + 3][tx << 2];
            float pr[4][4] = {{p0.x,p0.y,p0.z,p0.w},{p1.x,p1.y,p1.z,p1.w},
                              {p2.x,p2.y,p2.z,p2.w},{p3.x,p3.y,p3.z,p3.w}};
            float vr[4][4] = {{v0.x,v0.y,v0.z,v0.w},{v1.x,v1.y,v1.z,v1.w},
                              {v2.x,v2.y,v2.z,v2.w},{v3.x,v3.y,v3.z,v3.w}};
#pragma unroll
            for (int i = 0; i < 4; i++)
#pragma unroll
                for (int j = 0; j < 4; j++) {
                    float acc = Oa[i][j];
#pragma unroll
                    for (int n = 0; n < 4; n++)
                        acc = fmaf(pr[i][n], vr[n][j], acc);
                    Oa[i][j] = acc;
                }
        }
        __syncthreads();
    }

    // normalize + write [b,l,h*hd]
#pragma unroll
    for (int i = 0; i < 4; i++) {
        int row = q0 + (ty << 2) + i;
        float inv = 1.f / l_i[i];
        float4 o = make_float4(Oa[i][0] * inv, Oa[i][1] * inv,
                               Oa[i][2] * inv, Oa[i][3] * inv);
        *(float4*)&g_attn[(size_t)(b * L_ + row) * D_ + h * HD_ + (tx << 2)] = o;
    }
}

// ---------------- launch ----------------------------------------------------
extern "C" void kernel_launch(void* const* d_in, const int* in_sizes, int n_in,
                              void* d_out, int out_size)
{
    const float* q_in = (const float*)d_in[0];
    const float* k_in = (const float*)d_in[1];
    // d_in[2] = v_in (unused by reference), d_in[3] = mask (tril, hardcoded causal)
    const float* rope = (const float*)d_in[4];
    const float* Wq   = (const float*)d_in[5];
    const float* bq   = (const float*)d_in[6];
    const float* Wkv  = (const float*)d_in[7];
    const float* bkv  = (const float*)d_in[8];
    const float* Wp   = (const float*)d_in[9];
    const float* bp   = (const float*)d_in[10];
    float* out = (float*)d_out;

    float *qp, *kvp, *attn;
    cudaGetSymbolAddress((void**)&qp,   g_qp);
    cudaGetSymbolAddress((void**)&kvp,  g_kvp);
    cudaGetSymbolAddress((void**)&attn, g_attn);

    // 1) Q projection: [8192,1024] = q_in @ Wq + bq
    sgemm_bias_kernel<<<dim3(D_ / 128, BL_ / 128), 256>>>(q_in, Wq, bq, qp, BL_, D_, D_);
    // 2) KV projection: [8192,2048] = k_in @ Wkv + bkv
    sgemm_bias_kernel<<<dim3(2 * D_ / 128, BL_ / 128), 256>>>(k_in, Wkv, bkv, kvp, BL_, 2 * D_, D_);
    // 3) RoPE + split + transpose to [b,h,l,hd]
    rope_split_kernel<<<(B_ * H_ * L_ * 32) / 256, 256>>>(rope);
    // 4) causal flash attention
    cudaFuncSetAttribute(flash_kernel, cudaFuncAttributeMaxDynamicSharedMemorySize, FLASH_SMEM);
    flash_kernel<<<dim3(L_ / FBM, BH_), 256, FLASH_SMEM>>>();
    // 5) output projection: out = attn @ Wp + bp
    sgemm_bias_kernel<<<dim3(D_ / 128, BL_ / 128), 256>>>(attn, Wp, bp, out, BL_, D_, D_);
}